// round 13
// baseline (speedup 1.0000x reference)
#include <cuda_runtime.h>
#include <cuda_fp16.h>
#include <cuda_bf16.h>
#include <cstdint>
#include <cstddef>

// ---------------- problem constants ----------------
#define NE    50000
#define NB    1024
#define DIMK  2000
#define KPAD  2048
#define NCHUNK (KPAD / 64)          // 32 K-chunks of 64 fp16 (=128B rows)

#define SCALE_X   1048576.0f        // 2^20
#define SCALE_E   64.0f             // 2^6
#define INV_SCALE (1.0f / (1048576.0f * 64.0f))   // exact 2^-26

// GEMM tiling: M = batch, N = entities. One 512-thread CTA per SM.
#define TILE_MB 128                 // batch tile
#define TILE_NE 256                 // entity tile
#define MT_B (NB / TILE_MB)                   // 8
#define NT_E ((NE + TILE_NE - 1) / TILE_NE)   // 196
#define NTHREADS 512

// SMEM (dynamic): 3-stage pipeline. A = X tile, B = E tile. 128B per row.
#define STAGES  3
#define A_BYTES (TILE_MB * 128)               // 16384 / stage
#define B_BYTES (TILE_NE * 128)               // 32768 / stage
#define SM_A0   0
#define SM_B0   (STAGES * A_BYTES)            // 49152
#define SMEM_TOTAL (SM_B0 + STAGES * B_BYTES) // 147456 (144 KB/CTA)

// ---------------- static scratch (no runtime allocation) ----------------
static __device__ __align__(1024) __half g_E16[(size_t)NE * KPAD];   // ~200 MB
static __device__ __align__(1024) __half g_X16[(size_t)NB * KPAD];   // 4 MB
static __device__ float g_norms[6][NB];

// ---------------- helpers (sm_80-era ISA only: no tcgen05 on plain sm_103) --
__device__ __forceinline__ uint32_t smem_u32(const void* p) {
    uint32_t a;
    asm("{ .reg .u64 t; cvta.to.shared.u64 t, %1; cvt.u32.u64 %0, t; }" : "=r"(a) : "l"(p));
    return a;
}
__device__ __forceinline__ void cp_async16(uint32_t dst, const void* src) {
    asm volatile("cp.async.cg.shared.global [%0], [%1], 16;" :: "r"(dst), "l"(src) : "memory");
}
__device__ __forceinline__ void cp_commit() {
    asm volatile("cp.async.commit_group;" ::: "memory");
}
__device__ __forceinline__ uint32_t sw128(uint32_t off) {   // Swizzle<3,4,3>
    return off ^ ((off >> 3) & 0x70);
}
__device__ __forceinline__ void ldsm_x4(uint32_t& r0, uint32_t& r1, uint32_t& r2, uint32_t& r3,
                                        uint32_t addr) {
    asm volatile("ldmatrix.sync.aligned.m8n8.x4.shared.b16 {%0,%1,%2,%3}, [%4];"
                 : "=r"(r0), "=r"(r1), "=r"(r2), "=r"(r3) : "r"(addr));
}
__device__ __forceinline__ void mma16816(float& c0, float& c1, float& c2, float& c3,
                                         uint32_t a0, uint32_t a1, uint32_t a2, uint32_t a3,
                                         uint32_t b0, uint32_t b1) {
    asm volatile("mma.sync.aligned.m16n8k16.row.col.f32.f16.f16.f32 "
                 "{%0,%1,%2,%3}, {%4,%5,%6,%7}, {%8,%9}, {%0,%1,%2,%3};"
                 : "+f"(c0), "+f"(c1), "+f"(c2), "+f"(c3)
                 : "r"(a0), "r"(a1), "r"(a2), "r"(a3), "r"(b0), "r"(b1));
}

// =====================================================================
// Kernel 1: gather h/r/t, complex product -> g_X16 (fp16 * 2^20, K-padded)
//           plus the 6 per-batch norm sums
// =====================================================================
__global__ void __launch_bounds__(256) x_norm_kernel(
    const int* __restrict__ heads, const int* __restrict__ rels, const int* __restrict__ tails,
    const float* __restrict__ E, const float* __restrict__ R)
{
    int b = blockIdx.x;
    int tid = threadIdx.x, lane = tid & 31, wid = tid >> 5;

    const float* hrow = E + (size_t)heads[b] * DIMK;
    const float* rrow = R + (size_t)rels[b]  * DIMK;
    const float* trow = E + (size_t)tails[b] * DIMK;
    __half* xrow = g_X16 + (size_t)b * KPAD;

    float sh = 0.f, sr = 0.f, st = 0.f, shr = 0.f, srt = 0.f, sth = 0.f;

    for (int d = tid; d < KPAD / 2; d += 256) {
        if (d < DIMK / 2) {
            float2 h = *(const float2*)(hrow + 2 * d);
            float2 r = *(const float2*)(rrow + 2 * d);
            float2 t = *(const float2*)(trow + 2 * d);
            float h2 = h.x * h.x + h.y * h.y;
            float r2 = r.x * r.x + r.y * r.y;
            float t2 = t.x * t.x + t.y * t.y;
            sh += h2; sr += r2; st += t2;
            shr += h2 * r2; srt += r2 * t2; sth += t2 * h2;
            float x0 = h.x * r.x - h.y * r.y;
            float x1 = h.x * r.y + h.y * r.x;
            *(__half2*)(xrow + 2 * d) = __floats2half2_rn(x0 * SCALE_X, x1 * SCALE_X);
        } else {
            *(__half2*)(xrow + 2 * d) = __floats2half2_rn(0.f, 0.f);
        }
    }

    #pragma unroll
    for (int o = 16; o > 0; o >>= 1) {
        sh  += __shfl_down_sync(0xffffffffu, sh,  o);
        sr  += __shfl_down_sync(0xffffffffu, sr,  o);
        st  += __shfl_down_sync(0xffffffffu, st,  o);
        shr += __shfl_down_sync(0xffffffffu, shr, o);
        srt += __shfl_down_sync(0xffffffffu, srt, o);
        sth += __shfl_down_sync(0xffffffffu, sth, o);
    }
    __shared__ float red[6][8];
    if (lane == 0) {
        red[0][wid] = sh;  red[1][wid] = sr;  red[2][wid] = st;
        red[3][wid] = shr; red[4][wid] = srt; red[5][wid] = sth;
    }
    __syncthreads();
    if (tid == 0) {
        #pragma unroll
        for (int j = 0; j < 6; j++) {
            float s = 0.f;
            #pragma unroll
            for (int w = 0; w < 8; w++) s += red[j][w];
            g_norms[j][b] = s;
        }
    }
}

// =====================================================================
// Kernel 2: entity_weight fp32 [NE,2000] -> fp16*2^6 [NE,2048] (zero-padded)
// =====================================================================
__global__ void __launch_bounds__(256) convert_kernel(const float* __restrict__ E)
{
    int row = blockIdx.x;
    int c0 = threadIdx.x * 8;
    __half* dst = g_E16 + (size_t)row * KPAD + c0;
    if (c0 < DIMK) {
        const float* src = E + (size_t)row * DIMK + c0;
        float4 v0 = *(const float4*)(src);
        float4 v1 = *(const float4*)(src + 4);
        __half2 h0 = __floats2half2_rn(v0.x * SCALE_E, v0.y * SCALE_E);
        __half2 h1 = __floats2half2_rn(v0.z * SCALE_E, v0.w * SCALE_E);
        __half2 h2 = __floats2half2_rn(v1.x * SCALE_E, v1.y * SCALE_E);
        __half2 h3 = __floats2half2_rn(v1.z * SCALE_E, v1.w * SCALE_E);
        uint4 p;
        p.x = *(uint32_t*)&h0; p.y = *(uint32_t*)&h1;
        p.z = *(uint32_t*)&h2; p.w = *(uint32_t*)&h3;
        *(uint4*)dst = p;
    } else {
        *(uint4*)dst = make_uint4(0u, 0u, 0u, 0u);
    }
}

// =====================================================================
// Kernel 3: factors. Analytically factor3==factor1, factor4==factor2.
// =====================================================================
__global__ void __launch_bounds__(256) factors_kernel(float* __restrict__ out4)
{
    int tid = threadIdx.x, lane = tid & 31, wid = tid >> 5;
    float a = 0.f, c = 0.f;
    for (int i = tid; i < NB; i += 256) {
        a += g_norms[0][i] + g_norms[1][i] + g_norms[2][i];
        c += g_norms[3][i] + g_norms[4][i] + g_norms[5][i];
    }
    #pragma unroll
    for (int o = 16; o > 0; o >>= 1) {
        a += __shfl_down_sync(0xffffffffu, a, o);
        c += __shfl_down_sync(0xffffffffu, c, o);
    }
    __shared__ float sa[8], sc[8];
    if (lane == 0) { sa[wid] = a; sc[wid] = c; }
    __syncthreads();
    if (tid == 0) {
        float fa = 0.f, fc = 0.f;
        #pragma unroll
        for (int w = 0; w < 8; w++) { fa += sa[w]; fc += sc[w]; }
        fa /= (float)NB; fc /= (float)NB;
        out4[0] = fa; out4[1] = fc; out4[2] = fa; out4[3] = fc;
    }
}

// =====================================================================
// Kernel 4: scores[b, e] = sum_k X16[b,k] * E16[e,k]
// mma.sync m16n8k16 fp16->fp32, 3-stage cp.async pipeline.
// ONE 512-thread CTA / SM, tile 128(batch) x 256(entity), warp grid 4x4,
// warp tile 32x64. Shared-port traffic per chunk = 192KB LDSM + 48KB fill
// = 1920 cyc < 2048 tensor cyc -> tensor pipe becomes the binding pipe.
// =====================================================================
__global__ void __launch_bounds__(NTHREADS, 1) gemm_kernel(float* __restrict__ out)
{
    extern __shared__ char smem[];
    uint32_t sbase = smem_u32(smem);
    int tid = threadIdx.x;
    int wid = tid >> 5, lane = tid & 31;

    int nt = (int)(blockIdx.x >> 3);          // entity tile
    int mt = (int)(blockIdx.x & 7);           // batch tile
    int b0 = mt * TILE_MB;
    int e0 = nt * TILE_NE;

    int wm0 = (wid & 3) * 32;                 // warp batch offset (0..96)
    int wn0 = (wid >> 2) * 64;                // warp entity offset (0..192)

    // ---- async load of chunk c into stage s (6 x cp.async16 per thread) ----
    auto load_chunk = [&](int c, int s) {
        uint32_t abase = sbase + SM_A0 + s * A_BYTES;
        #pragma unroll
        for (int i = 0; i < 2; i++) {
            int ch = tid + i * NTHREADS;
            int row = ch >> 3, j = ch & 7;
            const __half* src = g_X16 + (size_t)(b0 + row) * KPAD + c * 64 + j * 8;
            cp_async16(abase + sw128((uint32_t)(row * 128 + j * 16)), src);
        }
        uint32_t bbase = sbase + SM_B0 + s * B_BYTES;
        #pragma unroll
        for (int i = 0; i < 4; i++) {
            int ch = tid + i * NTHREADS;
            int row = ch >> 3, j = ch & 7;
            int ge = e0 + row; if (ge >= NE) ge = NE - 1;   // clamp tail tile
            const __half* src = g_E16 + (size_t)ge * KPAD + c * 64 + j * 8;
            cp_async16(bbase + sw128((uint32_t)(row * 128 + j * 16)), src);
        }
        cp_commit();
    };

    float acc[2][8][4];
    #pragma unroll
    for (int mi = 0; mi < 2; mi++)
        #pragma unroll
        for (int nj = 0; nj < 8; nj++)
            #pragma unroll
            for (int q = 0; q < 4; q++) acc[mi][nj][q] = 0.f;

    load_chunk(0, 0);
    load_chunk(1, 1);

    // ldmatrix lane address components
    int a_r = lane & 15;
    int a_k = (lane >> 4) << 4;
    int b_r = (lane & 7) + ((lane >> 4) & 1) * 8;
    int b_k = ((lane >> 3) & 1) << 4;

    // one k16-slice of compute on a stage
    auto compute_ks = [&](uint32_t abase, uint32_t bbase, int ks) {
        uint32_t a[2][4];
        #pragma unroll
        for (int mi = 0; mi < 2; mi++) {
            uint32_t row = (uint32_t)(wm0 + mi * 16 + a_r);
            ldsm_x4(a[mi][0], a[mi][1], a[mi][2], a[mi][3],
                    abase + sw128(row * 128 + (uint32_t)(ks * 32 + a_k)));
        }
        uint32_t bfr[8][2];
        #pragma unroll
        for (int ni = 0; ni < 4; ni++) {
            uint32_t r0, r1, r2, r3;
            uint32_t row = (uint32_t)(wn0 + ni * 16 + b_r);
            ldsm_x4(r0, r1, r2, r3,
                    bbase + sw128(row * 128 + (uint32_t)(ks * 32 + b_k)));
            bfr[2 * ni][0] = r0;  bfr[2 * ni][1] = r1;
            bfr[2 * ni + 1][0] = r2; bfr[2 * ni + 1][1] = r3;
        }
        #pragma unroll
        for (int mi = 0; mi < 2; mi++)
            #pragma unroll
            for (int nj = 0; nj < 8; nj++)
                mma16816(acc[mi][nj][0], acc[mi][nj][1], acc[mi][nj][2], acc[mi][nj][3],
                         a[mi][0], a[mi][1], a[mi][2], a[mi][3],
                         bfr[nj][0], bfr[nj][1]);
    };

    #pragma unroll 1
    for (int c = 0; c < NCHUNK; c++) {
        if (c < NCHUNK - 1) asm volatile("cp.async.wait_group 1;" ::: "memory");
        else                asm volatile("cp.async.wait_group 0;" ::: "memory");
        __syncthreads();

        // stage (c+2)%3 == (c-1)%3 was fully consumed before this barrier
        if (c + 2 < NCHUNK) load_chunk(c + 2, (c + 2) % STAGES);

        int s = c % STAGES;
        uint32_t abase = sbase + SM_A0 + s * A_BYTES;
        uint32_t bbase = sbase + SM_B0 + s * B_BYTES;

        if (c < NCHUNK - 1) {
            #pragma unroll
            for (int ks = 0; ks < 4; ks++) compute_ks(abase, bbase, ks);
        } else {
            // last chunk: cols 2000..2047 are zero-padded -> only ks=0 is real
            compute_ks(abase, bbase, 0);
        }
    }

    // ---- epilogue: streaming float2 stores (cols = contiguous entities) ----
    int g = lane >> 2, tq = lane & 3;
    #pragma unroll
    for (int mi = 0; mi < 2; mi++) {
        int brow0 = b0 + wm0 + mi * 16 + g;
        #pragma unroll
        for (int nj = 0; nj < 8; nj++) {
            int e = e0 + wn0 + nj * 8 + 2 * tq;
            if (e < NE) {
                float2 v0 = make_float2(acc[mi][nj][0] * INV_SCALE, acc[mi][nj][1] * INV_SCALE);
                float2 v1 = make_float2(acc[mi][nj][2] * INV_SCALE, acc[mi][nj][3] * INV_SCALE);
                __stcs((float2*)(out + (size_t)brow0 * NE + e), v0);
                __stcs((float2*)(out + (size_t)(brow0 + 8) * NE + e), v1);
            }
        }
    }
}

// =====================================================================
extern "C" void kernel_launch(void* const* d_in, const int* in_sizes, int n_in,
                              void* d_out, int out_size)
{
    const int*   heads = (const int*)d_in[0];
    const int*   rels  = (const int*)d_in[1];
    const int*   tails = (const int*)d_in[2];
    const float* E     = (const float*)d_in[3];
    const float* R     = (const float*)d_in[4];
    float* out = (float*)d_out;

    cudaFuncSetAttribute(gemm_kernel, cudaFuncAttributeMaxDynamicSharedMemorySize, SMEM_TOTAL);

    convert_kernel<<<NE, 256>>>(E);
    x_norm_kernel<<<NB, 256>>>(heads, rels, tails, E, R);
    factors_kernel<<<1, 256>>>(out + (size_t)NB * NE);
    gemm_kernel<<<NT_E * MT_B, NTHREADS, SMEM_TOTAL>>>(out);
}

// round 15
// speedup vs baseline: 1.1350x; 1.1350x over previous
#include <cuda_runtime.h>
#include <cuda_fp16.h>
#include <cuda_bf16.h>
#include <cstdint>
#include <cstddef>

// ---------------- problem constants ----------------
#define NE    50000
#define NB    1024
#define DIMK  2000
#define KPAD  2048
#define NCHUNK (KPAD / 64)          // 32 K-chunks of 64 fp16 (=128B rows)

#define SCALE_X   1048576.0f        // 2^20
#define SCALE_E   64.0f             // 2^6
#define INV_SCALE (1.0f / (1048576.0f * 64.0f))   // exact 2^-26

// GEMM tiling: M = batch, N = entities. 2 CTAs/SM (8-warp barrier domains).
#define TILE_MB 128                 // batch tile
#define TILE_NE 128                 // entity tile
#define MT_B (NB / TILE_MB)                   // 8
#define NT_E ((NE + TILE_NE - 1) / TILE_NE)   // 391

// SMEM (dynamic): 3-stage pipeline. A = X tile, B = E tile. 128B per row.
#define STAGES  3
#define A_BYTES (TILE_MB * 128)               // 16384 / stage
#define B_BYTES (TILE_NE * 128)               // 16384 / stage
#define SM_A0   0
#define SM_B0   (STAGES * A_BYTES)            // 49152
#define SMEM_TOTAL (SM_B0 + STAGES * B_BYTES) // 98304 (96 KB/CTA, 192 KB/SM @2)

// ---------------- static scratch (no runtime allocation) ----------------
static __device__ __align__(1024) __half g_E16[(size_t)NE * KPAD];   // ~200 MB
static __device__ __align__(1024) __half g_X16[(size_t)NB * KPAD];   // 4 MB
static __device__ float g_norms[6][NB];

// ---------------- helpers (sm_80-era ISA only: no tcgen05 on plain sm_103) --
__device__ __forceinline__ uint32_t smem_u32(const void* p) {
    uint32_t a;
    asm("{ .reg .u64 t; cvta.to.shared.u64 t, %1; cvt.u32.u64 %0, t; }" : "=r"(a) : "l"(p));
    return a;
}
__device__ __forceinline__ void cp_async16(uint32_t dst, const void* src) {
    asm volatile("cp.async.cg.shared.global [%0], [%1], 16;" :: "r"(dst), "l"(src) : "memory");
}
__device__ __forceinline__ void cp_commit() {
    asm volatile("cp.async.commit_group;" ::: "memory");
}
__device__ __forceinline__ uint32_t sw128(uint32_t off) {   // Swizzle<3,4,3>
    return off ^ ((off >> 3) & 0x70);
}
__device__ __forceinline__ void ldsm_x4(uint32_t& r0, uint32_t& r1, uint32_t& r2, uint32_t& r3,
                                        uint32_t addr) {
    asm volatile("ldmatrix.sync.aligned.m8n8.x4.shared.b16 {%0,%1,%2,%3}, [%4];"
                 : "=r"(r0), "=r"(r1), "=r"(r2), "=r"(r3) : "r"(addr));
}
__device__ __forceinline__ void mma16816(float& c0, float& c1, float& c2, float& c3,
                                         uint32_t a0, uint32_t a1, uint32_t a2, uint32_t a3,
                                         uint32_t b0, uint32_t b1) {
    asm volatile("mma.sync.aligned.m16n8k16.row.col.f32.f16.f16.f32 "
                 "{%0,%1,%2,%3}, {%4,%5,%6,%7}, {%8,%9}, {%0,%1,%2,%3};"
                 : "+f"(c0), "+f"(c1), "+f"(c2), "+f"(c3)
                 : "r"(a0), "r"(a1), "r"(a2), "r"(a3), "r"(b0), "r"(b1));
}

// =====================================================================
// Kernel 1 (MERGED): blocks [0, NE) convert entity_weight fp32 -> fp16*2^6
// into g_E16 [NE,2048]; blocks [NE, NE+NB) do the gather + complex product
// -> g_X16 and the 6 per-batch norm sums. x_norm runs in convert's shadow.
// =====================================================================
__global__ void __launch_bounds__(256) prep_kernel(
    const int* __restrict__ heads, const int* __restrict__ rels, const int* __restrict__ tails,
    const float* __restrict__ E, const float* __restrict__ R)
{
    int blk = blockIdx.x;
    int tid = threadIdx.x;

    if (blk < NE) {
        // ---- convert path ----
        int row = blk;
        int c0 = tid * 8;
        __half* dst = g_E16 + (size_t)row * KPAD + c0;
        if (c0 < DIMK) {
            const float* src = E + (size_t)row * DIMK + c0;
            float4 v0 = *(const float4*)(src);
            float4 v1 = *(const float4*)(src + 4);
            __half2 h0 = __floats2half2_rn(v0.x * SCALE_E, v0.y * SCALE_E);
            __half2 h1 = __floats2half2_rn(v0.z * SCALE_E, v0.w * SCALE_E);
            __half2 h2 = __floats2half2_rn(v1.x * SCALE_E, v1.y * SCALE_E);
            __half2 h3 = __floats2half2_rn(v1.z * SCALE_E, v1.w * SCALE_E);
            uint4 p;
            p.x = *(uint32_t*)&h0; p.y = *(uint32_t*)&h1;
            p.z = *(uint32_t*)&h2; p.w = *(uint32_t*)&h3;
            *(uint4*)dst = p;
        } else {
            *(uint4*)dst = make_uint4(0u, 0u, 0u, 0u);
        }
        return;
    }

    // ---- x_norm path ----
    int b = blk - NE;
    int lane = tid & 31, wid = tid >> 5;

    const float* hrow = E + (size_t)heads[b] * DIMK;
    const float* rrow = R + (size_t)rels[b]  * DIMK;
    const float* trow = E + (size_t)tails[b] * DIMK;
    __half* xrow = g_X16 + (size_t)b * KPAD;

    float sh = 0.f, sr = 0.f, st = 0.f, shr = 0.f, srt = 0.f, sth = 0.f;

    for (int d = tid; d < KPAD / 2; d += 256) {
        if (d < DIMK / 2) {
            float2 h = *(const float2*)(hrow + 2 * d);
            float2 r = *(const float2*)(rrow + 2 * d);
            float2 t = *(const float2*)(trow + 2 * d);
            float h2 = h.x * h.x + h.y * h.y;
            float r2 = r.x * r.x + r.y * r.y;
            float t2 = t.x * t.x + t.y * t.y;
            sh += h2; sr += r2; st += t2;
            shr += h2 * r2; srt += r2 * t2; sth += t2 * h2;
            float x0 = h.x * r.x - h.y * r.y;
            float x1 = h.x * r.y + h.y * r.x;
            *(__half2*)(xrow + 2 * d) = __floats2half2_rn(x0 * SCALE_X, x1 * SCALE_X);
        } else {
            *(__half2*)(xrow + 2 * d) = __floats2half2_rn(0.f, 0.f);
        }
    }

    #pragma unroll
    for (int o = 16; o > 0; o >>= 1) {
        sh  += __shfl_down_sync(0xffffffffu, sh,  o);
        sr  += __shfl_down_sync(0xffffffffu, sr,  o);
        st  += __shfl_down_sync(0xffffffffu, st,  o);
        shr += __shfl_down_sync(0xffffffffu, shr, o);
        srt += __shfl_down_sync(0xffffffffu, srt, o);
        sth += __shfl_down_sync(0xffffffffu, sth, o);
    }
    __shared__ float red[6][8];
    if (lane == 0) {
        red[0][wid] = sh;  red[1][wid] = sr;  red[2][wid] = st;
        red[3][wid] = shr; red[4][wid] = srt; red[5][wid] = sth;
    }
    __syncthreads();
    if (tid == 0) {
        #pragma unroll
        for (int j = 0; j < 6; j++) {
            float s = 0.f;
            #pragma unroll
            for (int w = 0; w < 8; w++) s += red[j][w];
            g_norms[j][b] = s;
        }
    }
}

// =====================================================================
// Kernel 2: factors. Analytically factor3==factor1, factor4==factor2.
// =====================================================================
__global__ void __launch_bounds__(256) factors_kernel(float* __restrict__ out4)
{
    int tid = threadIdx.x, lane = tid & 31, wid = tid >> 5;
    float a = 0.f, c = 0.f;
    for (int i = tid; i < NB; i += 256) {
        a += g_norms[0][i] + g_norms[1][i] + g_norms[2][i];
        c += g_norms[3][i] + g_norms[4][i] + g_norms[5][i];
    }
    #pragma unroll
    for (int o = 16; o > 0; o >>= 1) {
        a += __shfl_down_sync(0xffffffffu, a, o);
        c += __shfl_down_sync(0xffffffffu, c, o);
    }
    __shared__ float sa[8], sc[8];
    if (lane == 0) { sa[wid] = a; sc[wid] = c; }
    __syncthreads();
    if (tid == 0) {
        float fa = 0.f, fc = 0.f;
        #pragma unroll
        for (int w = 0; w < 8; w++) { fa += sa[w]; fc += sc[w]; }
        fa /= (float)NB; fc /= (float)NB;
        out4[0] = fa; out4[1] = fc; out4[2] = fa; out4[3] = fc;
    }
}

// =====================================================================
// Kernel 3: scores[b, e] = sum_k X16[b,k] * E16[e,k]
// mma.sync m16n8k16 fp16->fp32, 3-stage cp.async pipeline, 2 CTAs/SM
// (8-warp barrier domains — the R7 winner). NEW: the next chunk's fill
// burst is issued AFTER the first k16-slice so MMAs restart immediately
// after the barrier instead of waiting behind 32 LDGSTS issues.
// =====================================================================
__global__ void __launch_bounds__(256, 2) gemm_kernel(float* __restrict__ out)
{
    extern __shared__ char smem[];
    uint32_t sbase = smem_u32(smem);
    int tid = threadIdx.x;
    int wid = tid >> 5, lane = tid & 31;

    int nt = (int)(blockIdx.x >> 3);          // entity tile
    int mt = (int)(blockIdx.x & 7);           // batch tile
    int b0 = mt * TILE_MB;
    int e0 = nt * TILE_NE;

    int wm0 = (wid & 1) * 64;                 // warp batch offset (0/64)
    int wn0 = (wid >> 1) * 32;                // warp entity offset (0..96)

    // ---- async load of chunk c into stage s (8 x cp.async16 per thread) ----
    auto load_chunk = [&](int c, int s) {
        uint32_t abase = sbase + SM_A0 + s * A_BYTES;
        #pragma unroll
        for (int i = 0; i < 4; i++) {
            int ch = tid + i * 256;
            int row = ch >> 3, j = ch & 7;
            const __half* src = g_X16 + (size_t)(b0 + row) * KPAD + c * 64 + j * 8;
            cp_async16(abase + sw128((uint32_t)(row * 128 + j * 16)), src);
        }
        uint32_t bbase = sbase + SM_B0 + s * B_BYTES;
        #pragma unroll
        for (int i = 0; i < 4; i++) {
            int ch = tid + i * 256;
            int row = ch >> 3, j = ch & 7;
            int ge = e0 + row; if (ge >= NE) ge = NE - 1;   // clamp tail tile
            const __half* src = g_E16 + (size_t)ge * KPAD + c * 64 + j * 8;
            cp_async16(bbase + sw128((uint32_t)(row * 128 + j * 16)), src);
        }
        cp_commit();
    };

    float acc[4][4][4];
    #pragma unroll
    for (int mi = 0; mi < 4; mi++)
        #pragma unroll
        for (int nj = 0; nj < 4; nj++)
            #pragma unroll
            for (int q = 0; q < 4; q++) acc[mi][nj][q] = 0.f;

    load_chunk(0, 0);
    load_chunk(1, 1);

    // ldmatrix lane address components
    int a_r = lane & 15;
    int a_k = (lane >> 4) << 4;
    int b_r = (lane & 7) + ((lane >> 4) & 1) * 8;
    int b_k = ((lane >> 3) & 1) << 4;

    // one k16-slice of compute on a stage
    auto compute_ks = [&](uint32_t abase, uint32_t bbase, int ks) {
        uint32_t a[4][4];
        #pragma unroll
        for (int mi = 0; mi < 4; mi++) {
            uint32_t row = (uint32_t)(wm0 + mi * 16 + a_r);
            ldsm_x4(a[mi][0], a[mi][1], a[mi][2], a[mi][3],
                    abase + sw128(row * 128 + (uint32_t)(ks * 32 + a_k)));
        }
        uint32_t bfr[4][2];
        #pragma unroll
        for (int ni = 0; ni < 2; ni++) {
            uint32_t r0, r1, r2, r3;
            uint32_t row = (uint32_t)(wn0 + ni * 16 + b_r);
            ldsm_x4(r0, r1, r2, r3,
                    bbase + sw128(row * 128 + (uint32_t)(ks * 32 + b_k)));
            bfr[2 * ni][0] = r0;  bfr[2 * ni][1] = r1;
            bfr[2 * ni + 1][0] = r2; bfr[2 * ni + 1][1] = r3;
        }
        #pragma unroll
        for (int mi = 0; mi < 4; mi++)
            #pragma unroll
            for (int nj = 0; nj < 4; nj++)
                mma16816(acc[mi][nj][0], acc[mi][nj][1], acc[mi][nj][2], acc[mi][nj][3],
                         a[mi][0], a[mi][1], a[mi][2], a[mi][3],
                         bfr[nj][0], bfr[nj][1]);
    };

    #pragma unroll 1
    for (int c = 0; c < NCHUNK; c++) {
        if (c < NCHUNK - 1) asm volatile("cp.async.wait_group 1;" ::: "memory");
        else                asm volatile("cp.async.wait_group 0;" ::: "memory");
        __syncthreads();

        int s = c % STAGES;
        uint32_t abase = sbase + SM_A0 + s * A_BYTES;
        uint32_t bbase = sbase + SM_B0 + s * B_BYTES;

        if (c < NCHUNK - 1) {
            // slice 0 first: tensor pipe restarts immediately post-barrier
            compute_ks(abase, bbase, 0);
            // then issue the next chunk's fill (stage (c+2)%3 held chunk c-1,
            // fully consumed before this iteration's barrier)
            if (c + 2 < NCHUNK) load_chunk(c + 2, (c + 2) % STAGES);
            #pragma unroll
            for (int ks = 1; ks < 4; ks++) compute_ks(abase, bbase, ks);
        } else {
            // last chunk: cols 2000..2047 are zero-padded -> only ks=0 is real
            compute_ks(abase, bbase, 0);
        }
    }

    // ---- epilogue: streaming float2 stores (cols = contiguous entities) ----
    int g = lane >> 2, tq = lane & 3;
    #pragma unroll
    for (int mi = 0; mi < 4; mi++) {
        int brow0 = b0 + wm0 + mi * 16 + g;
        #pragma unroll
        for (int nj = 0; nj < 4; nj++) {
            int e = e0 + wn0 + nj * 8 + 2 * tq;
            if (e < NE) {
                float2 v0 = make_float2(acc[mi][nj][0] * INV_SCALE, acc[mi][nj][1] * INV_SCALE);
                float2 v1 = make_float2(acc[mi][nj][2] * INV_SCALE, acc[mi][nj][3] * INV_SCALE);
                __stcs((float2*)(out + (size_t)brow0 * NE + e), v0);
                __stcs((float2*)(out + (size_t)(brow0 + 8) * NE + e), v1);
            }
        }
    }
}

// =====================================================================
extern "C" void kernel_launch(void* const* d_in, const int* in_sizes, int n_in,
                              void* d_out, int out_size)
{
    const int*   heads = (const int*)d_in[0];
    const int*   rels  = (const int*)d_in[1];
    const int*   tails = (const int*)d_in[2];
    const float* E     = (const float*)d_in[3];
    const float* R     = (const float*)d_in[4];
    float* out = (float*)d_out;

    cudaFuncSetAttribute(gemm_kernel, cudaFuncAttributeMaxDynamicSharedMemorySize, SMEM_TOTAL);

    prep_kernel<<<NE + NB, 256>>>(heads, rels, tails, E, R);
    factors_kernel<<<1, 256>>>(out + (size_t)NB * NE);
    gemm_kernel<<<NT_E * MT_B, 256, SMEM_TOTAL>>>(out);
}

// round 16
// speedup vs baseline: 1.1561x; 1.0186x over previous
#include <cuda_runtime.h>
#include <cuda_fp16.h>
#include <cuda_bf16.h>
#include <cstdint>
#include <cstddef>

// ---------------- problem constants ----------------
#define NE    50000
#define NB    1024
#define DIMK  2000
#define KPAD  2048
#define NCHUNK (KPAD / 64)          // 32 K-chunks of 64 fp16 (=128B rows)

#define SCALE_X   1048576.0f        // 2^20
#define SCALE_E   64.0f             // 2^6
#define INV_SCALE (1.0f / (1048576.0f * 64.0f))   // exact 2^-26

// GEMM tiling: M = batch, N = entities.
// 2 CTAs/SM of 128 threads (4-warp barrier domains), warp tile 64x64.
#define TILE_MB 128                 // batch tile
#define TILE_NE 128                 // entity tile
#define MT_B (NB / TILE_MB)                   // 8
#define NT_E ((NE + TILE_NE - 1) / TILE_NE)   // 391
#define GTHREADS 128

// SMEM (dynamic): 3-stage pipeline. A = X tile, B = E tile. 128B per row.
#define STAGES  3
#define A_BYTES (TILE_MB * 128)               // 16384 / stage
#define B_BYTES (TILE_NE * 128)               // 16384 / stage
#define SM_A0   0
#define SM_B0   (STAGES * A_BYTES)            // 49152
#define SMEM_TOTAL (SM_B0 + STAGES * B_BYTES) // 98304 (96 KB/CTA, 192 KB/SM @2)

// ---------------- static scratch (no runtime allocation) ----------------
static __device__ __align__(1024) __half g_E16[(size_t)NE * KPAD];   // ~200 MB
static __device__ __align__(1024) __half g_X16[(size_t)NB * KPAD];   // 4 MB
static __device__ float g_norms[6][NB];

// ---------------- helpers (sm_80-era ISA only: no tcgen05 on plain sm_103) --
__device__ __forceinline__ uint32_t smem_u32(const void* p) {
    uint32_t a;
    asm("{ .reg .u64 t; cvta.to.shared.u64 t, %1; cvt.u32.u64 %0, t; }" : "=r"(a) : "l"(p));
    return a;
}
__device__ __forceinline__ void cp_async16(uint32_t dst, const void* src) {
    asm volatile("cp.async.cg.shared.global [%0], [%1], 16;" :: "r"(dst), "l"(src) : "memory");
}
__device__ __forceinline__ void cp_commit() {
    asm volatile("cp.async.commit_group;" ::: "memory");
}
__device__ __forceinline__ uint32_t sw128(uint32_t off) {   // Swizzle<3,4,3>
    return off ^ ((off >> 3) & 0x70);
}
__device__ __forceinline__ void ldsm_x4(uint32_t& r0, uint32_t& r1, uint32_t& r2, uint32_t& r3,
                                        uint32_t addr) {
    asm volatile("ldmatrix.sync.aligned.m8n8.x4.shared.b16 {%0,%1,%2,%3}, [%4];"
                 : "=r"(r0), "=r"(r1), "=r"(r2), "=r"(r3) : "r"(addr));
}
__device__ __forceinline__ void mma16816(float& c0, float& c1, float& c2, float& c3,
                                         uint32_t a0, uint32_t a1, uint32_t a2, uint32_t a3,
                                         uint32_t b0, uint32_t b1) {
    asm volatile("mma.sync.aligned.m16n8k16.row.col.f32.f16.f16.f32 "
                 "{%0,%1,%2,%3}, {%4,%5,%6,%7}, {%8,%9}, {%0,%1,%2,%3};"
                 : "+f"(c0), "+f"(c1), "+f"(c2), "+f"(c3)
                 : "r"(a0), "r"(a1), "r"(a2), "r"(a3), "r"(b0), "r"(b1));
}

// =====================================================================
// Kernel 1 (MERGED): blocks [0, NE) convert entity_weight fp32 -> fp16*2^6
// into g_E16 [NE,2048]; blocks [NE, NE+NB) do the gather + complex product
// -> g_X16 and the 6 per-batch norm sums. (At HBM roofline — unchanged.)
// =====================================================================
__global__ void __launch_bounds__(256) prep_kernel(
    const int* __restrict__ heads, const int* __restrict__ rels, const int* __restrict__ tails,
    const float* __restrict__ E, const float* __restrict__ R)
{
    int blk = blockIdx.x;
    int tid = threadIdx.x;

    if (blk < NE) {
        // ---- convert path ----
        int row = blk;
        int c0 = tid * 8;
        __half* dst = g_E16 + (size_t)row * KPAD + c0;
        if (c0 < DIMK) {
            const float* src = E + (size_t)row * DIMK + c0;
            float4 v0 = *(const float4*)(src);
            float4 v1 = *(const float4*)(src + 4);
            __half2 h0 = __floats2half2_rn(v0.x * SCALE_E, v0.y * SCALE_E);
            __half2 h1 = __floats2half2_rn(v0.z * SCALE_E, v0.w * SCALE_E);
            __half2 h2 = __floats2half2_rn(v1.x * SCALE_E, v1.y * SCALE_E);
            __half2 h3 = __floats2half2_rn(v1.z * SCALE_E, v1.w * SCALE_E);
            uint4 p;
            p.x = *(uint32_t*)&h0; p.y = *(uint32_t*)&h1;
            p.z = *(uint32_t*)&h2; p.w = *(uint32_t*)&h3;
            *(uint4*)dst = p;
        } else {
            *(uint4*)dst = make_uint4(0u, 0u, 0u, 0u);
        }
        return;
    }

    // ---- x_norm path ----
    int b = blk - NE;
    int lane = tid & 31, wid = tid >> 5;

    const float* hrow = E + (size_t)heads[b] * DIMK;
    const float* rrow = R + (size_t)rels[b]  * DIMK;
    const float* trow = E + (size_t)tails[b] * DIMK;
    __half* xrow = g_X16 + (size_t)b * KPAD;

    float sh = 0.f, sr = 0.f, st = 0.f, shr = 0.f, srt = 0.f, sth = 0.f;

    for (int d = tid; d < KPAD / 2; d += 256) {
        if (d < DIMK / 2) {
            float2 h = *(const float2*)(hrow + 2 * d);
            float2 r = *(const float2*)(rrow + 2 * d);
            float2 t = *(const float2*)(trow + 2 * d);
            float h2 = h.x * h.x + h.y * h.y;
            float r2 = r.x * r.x + r.y * r.y;
            float t2 = t.x * t.x + t.y * t.y;
            sh += h2; sr += r2; st += t2;
            shr += h2 * r2; srt += r2 * t2; sth += t2 * h2;
            float x0 = h.x * r.x - h.y * r.y;
            float x1 = h.x * r.y + h.y * r.x;
            *(__half2*)(xrow + 2 * d) = __floats2half2_rn(x0 * SCALE_X, x1 * SCALE_X);
        } else {
            *(__half2*)(xrow + 2 * d) = __floats2half2_rn(0.f, 0.f);
        }
    }

    #pragma unroll
    for (int o = 16; o > 0; o >>= 1) {
        sh  += __shfl_down_sync(0xffffffffu, sh,  o);
        sr  += __shfl_down_sync(0xffffffffu, sr,  o);
        st  += __shfl_down_sync(0xffffffffu, st,  o);
        shr += __shfl_down_sync(0xffffffffu, shr, o);
        srt += __shfl_down_sync(0xffffffffu, srt, o);
        sth += __shfl_down_sync(0xffffffffu, sth, o);
    }
    __shared__ float red[6][8];
    if (lane == 0) {
        red[0][wid] = sh;  red[1][wid] = sr;  red[2][wid] = st;
        red[3][wid] = shr; red[4][wid] = srt; red[5][wid] = sth;
    }
    __syncthreads();
    if (tid == 0) {
        #pragma unroll
        for (int j = 0; j < 6; j++) {
            float s = 0.f;
            #pragma unroll
            for (int w = 0; w < 8; w++) s += red[j][w];
            g_norms[j][b] = s;
        }
    }
}

// =====================================================================
// Kernel 2: factors. Analytically factor3==factor1, factor4==factor2.
// =====================================================================
__global__ void __launch_bounds__(256) factors_kernel(float* __restrict__ out4)
{
    int tid = threadIdx.x, lane = tid & 31, wid = tid >> 5;
    float a = 0.f, c = 0.f;
    for (int i = tid; i < NB; i += 256) {
        a += g_norms[0][i] + g_norms[1][i] + g_norms[2][i];
        c += g_norms[3][i] + g_norms[4][i] + g_norms[5][i];
    }
    #pragma unroll
    for (int o = 16; o > 0; o >>= 1) {
        a += __shfl_down_sync(0xffffffffu, a, o);
        c += __shfl_down_sync(0xffffffffu, c, o);
    }
    __shared__ float sa[8], sc[8];
    if (lane == 0) { sa[wid] = a; sc[wid] = c; }
    __syncthreads();
    if (tid == 0) {
        float fa = 0.f, fc = 0.f;
        #pragma unroll
        for (int w = 0; w < 8; w++) { fa += sa[w]; fc += sc[w]; }
        fa /= (float)NB; fc /= (float)NB;
        out4[0] = fa; out4[1] = fc; out4[2] = fa; out4[3] = fc;
    }
}

// =====================================================================
// Kernel 3: scores[b, e] = sum_k X16[b,k] * E16[e,k]
// mma.sync m16n8k16 fp16->fp32, 3-stage cp.async, R13 deferred fill.
// NEW: 128-thread CTAs, 2/SM, warp grid 2x2, warp tile 64x64.
//  - port traffic/chunk/SM: LDSM 8w*(64+64)*128B=128KB + fill 64KB
//    = 1536 cyc < tensor 2048 cyc  -> tensor pipe binding
//  - per-warp MMA:LDSM = 32:8 -> one warp's MMA burst covers the
//    other SMSP warp's LDSM phase
//  - 4-warp barrier domains, unaligned across the two CTAs
// =====================================================================
__global__ void __launch_bounds__(GTHREADS, 2) gemm_kernel(float* __restrict__ out)
{
    extern __shared__ char smem[];
    uint32_t sbase = smem_u32(smem);
    int tid = threadIdx.x;
    int wid = tid >> 5, lane = tid & 31;

    int nt = (int)(blockIdx.x >> 3);          // entity tile
    int mt = (int)(blockIdx.x & 7);           // batch tile
    int b0 = mt * TILE_MB;
    int e0 = nt * TILE_NE;

    int wm0 = (wid & 1) * 64;                 // warp batch offset (0/64)
    int wn0 = (wid >> 1) * 64;                // warp entity offset (0/64)

    // ---- async load of chunk c into stage s (16 x cp.async16 per thread) ----
    auto load_chunk = [&](int c, int s) {
        uint32_t abase = sbase + SM_A0 + s * A_BYTES;
        #pragma unroll
        for (int i = 0; i < 8; i++) {
            int ch = tid + i * GTHREADS;
            int row = ch >> 3, j = ch & 7;
            const __half* src = g_X16 + (size_t)(b0 + row) * KPAD + c * 64 + j * 8;
            cp_async16(abase + sw128((uint32_t)(row * 128 + j * 16)), src);
        }
        uint32_t bbase = sbase + SM_B0 + s * B_BYTES;
        #pragma unroll
        for (int i = 0; i < 8; i++) {
            int ch = tid + i * GTHREADS;
            int row = ch >> 3, j = ch & 7;
            int ge = e0 + row; if (ge >= NE) ge = NE - 1;   // clamp tail tile
            const __half* src = g_E16 + (size_t)ge * KPAD + c * 64 + j * 8;
            cp_async16(bbase + sw128((uint32_t)(row * 128 + j * 16)), src);
        }
        cp_commit();
    };

    float acc[4][8][4];
    #pragma unroll
    for (int mi = 0; mi < 4; mi++)
        #pragma unroll
        for (int nj = 0; nj < 8; nj++)
            #pragma unroll
            for (int q = 0; q < 4; q++) acc[mi][nj][q] = 0.f;

    load_chunk(0, 0);
    load_chunk(1, 1);

    // ldmatrix lane address components
    int a_r = lane & 15;
    int a_k = (lane >> 4) << 4;
    int b_r = (lane & 7) + ((lane >> 4) & 1) * 8;
    int b_k = ((lane >> 3) & 1) << 4;

    // one k16-slice of compute on a stage (8 LDSM.x4 + 32 MMA)
    auto compute_ks = [&](uint32_t abase, uint32_t bbase, int ks) {
        uint32_t a[4][4];
        #pragma unroll
        for (int mi = 0; mi < 4; mi++) {
            uint32_t row = (uint32_t)(wm0 + mi * 16 + a_r);
            ldsm_x4(a[mi][0], a[mi][1], a[mi][2], a[mi][3],
                    abase + sw128(row * 128 + (uint32_t)(ks * 32 + a_k)));
        }
        uint32_t bfr[8][2];
        #pragma unroll
        for (int ni = 0; ni < 4; ni++) {
            uint32_t r0, r1, r2, r3;
            uint32_t row = (uint32_t)(wn0 + ni * 16 + b_r);
            ldsm_x4(r0, r1, r2, r3,
                    bbase + sw128(row * 128 + (uint32_t)(ks * 32 + b_k)));
            bfr[2 * ni][0] = r0;  bfr[2 * ni][1] = r1;
            bfr[2 * ni + 1][0] = r2; bfr[2 * ni + 1][1] = r3;
        }
        #pragma unroll
        for (int mi = 0; mi < 4; mi++)
            #pragma unroll
            for (int nj = 0; nj < 8; nj++)
                mma16816(acc[mi][nj][0], acc[mi][nj][1], acc[mi][nj][2], acc[mi][nj][3],
                         a[mi][0], a[mi][1], a[mi][2], a[mi][3],
                         bfr[nj][0], bfr[nj][1]);
    };

    #pragma unroll 1
    for (int c = 0; c < NCHUNK; c++) {
        if (c < NCHUNK - 1) asm volatile("cp.async.wait_group 1;" ::: "memory");
        else                asm volatile("cp.async.wait_group 0;" ::: "memory");
        __syncthreads();

        int s = c % STAGES;
        uint32_t abase = sbase + SM_A0 + s * A_BYTES;
        uint32_t bbase = sbase + SM_B0 + s * B_BYTES;

        if (c < NCHUNK - 1) {
            // slice 0 first: tensor pipe restarts immediately post-barrier
            compute_ks(abase, bbase, 0);
            // then issue the next chunk's fill (stage (c+2)%3 held chunk c-1,
            // fully consumed before this iteration's barrier)
            if (c + 2 < NCHUNK) load_chunk(c + 2, (c + 2) % STAGES);
            #pragma unroll
            for (int ks = 1; ks < 4; ks++) compute_ks(abase, bbase, ks);
        } else {
            // last chunk: cols 2000..2047 are zero-padded -> only ks=0 is real
            compute_ks(abase, bbase, 0);
        }
    }

    // ---- epilogue: streaming float2 stores (cols = contiguous entities) ----
    int g = lane >> 2, tq = lane & 3;
    #pragma unroll
    for (int mi = 0; mi < 4; mi++) {
        int brow0 = b0 + wm0 + mi * 16 + g;
        #pragma unroll
        for (int nj = 0; nj < 8; nj++) {
            int e = e0 + wn0 + nj * 8 + 2 * tq;
            if (e < NE) {
                float2 v0 = make_float2(acc[mi][nj][0] * INV_SCALE, acc[mi][nj][1] * INV_SCALE);
                float2 v1 = make_float2(acc[mi][nj][2] * INV_SCALE, acc[mi][nj][3] * INV_SCALE);
                __stcs((float2*)(out + (size_t)brow0 * NE + e), v0);
                __stcs((float2*)(out + (size_t)(brow0 + 8) * NE + e), v1);
            }
        }
    }
}

// =====================================================================
extern "C" void kernel_launch(void* const* d_in, const int* in_sizes, int n_in,
                              void* d_out, int out_size)
{
    const int*   heads = (const int*)d_in[0];
    const int*   rels  = (const int*)d_in[1];
    const int*   tails = (const int*)d_in[2];
    const float* E     = (const float*)d_in[3];
    const float* R     = (const float*)d_in[4];
    float* out = (float*)d_out;

    cudaFuncSetAttribute(gemm_kernel, cudaFuncAttributeMaxDynamicSharedMemorySize, SMEM_TOTAL);

    prep_kernel<<<NE + NB, 256>>>(heads, rels, tails, E, R);
    factors_kernel<<<1, 256>>>(out + (size_t)NB * NE);
    gemm_kernel<<<NT_E * MT_B, GTHREADS, SMEM_TOTAL>>>(out);
}